// round 1
// baseline (speedup 1.0000x reference)
#include <cuda_runtime.h>
#include <cuda_bf16.h>

#define NN 8192
#define DD 256
#define EE 131072

#define BM 64
#define BN 64
#define BK 32

// Scratch (static device allocations — allowed)
__device__ float g_bufY[NN * DD];   // matmul output / h buffer
__device__ float g_bufE[NN * DD];   // current embedding buffer
__device__ float g_rowsum[NN];
__device__ float g_deg[NN];         // deg, then dinv in-place

// ---------------------------------------------------------------------------
// Tiled fp32 matmul: Y[M=8192 x 256] = A[M x K](lda) @ B[K x 256]
// Optionally writes per-row sums of A into rowsum (blocks with blockIdx.x==0).
// Grid: (4, 128), block: 256 threads, each computes 4x4.
// ---------------------------------------------------------------------------
__global__ __launch_bounds__(256) void mm_kernel(
    const float* __restrict__ A, int lda,
    const float* __restrict__ B,
    float* __restrict__ Y, int K,
    float* __restrict__ rowsum)
{
    __shared__ float As[BM][BK + 4];   // +4 pad: conflict-free stores, 16B aligned
    __shared__ float Bs[BK][BN];

    const int t = threadIdx.x;
    const int rowBase = blockIdx.y * BM;
    const int colBase = blockIdx.x * BN;
    const int tx = t & 15;        // col group
    const int ty = t >> 4;        // row group

    // A-tile load mapping: each thread loads 8 consecutive k of one row
    const int arow  = t >> 2;           // 0..63
    const int akoff = (t & 3) * 8;      // 0,8,16,24
    // B-tile load mapping: each thread loads 8 consecutive cols of one k-row
    const int bk    = t >> 3;           // 0..31
    const int bjoff = (t & 7) * 8;      // 0..56

    float acc[4][4] = {};
    float rsum = 0.0f;

    const float* Aptr = A + (size_t)(rowBase + arow) * lda + akoff;
    const float* Bptr = B + (size_t)bk * DD + colBase + bjoff;

    for (int k0 = 0; k0 < K; k0 += BK) {
        float4 a0 = *(const float4*)(Aptr + k0);
        float4 a1 = *(const float4*)(Aptr + k0 + 4);
        *(float4*)&As[arow][akoff]     = a0;
        *(float4*)&As[arow][akoff + 4] = a1;
        rsum += a0.x + a0.y + a0.z + a0.w + a1.x + a1.y + a1.z + a1.w;

        float4 b0 = *(const float4*)(Bptr + (size_t)k0 * DD);
        float4 b1 = *(const float4*)(Bptr + (size_t)k0 * DD + 4);
        *(float4*)&Bs[bk][bjoff]     = b0;
        *(float4*)&Bs[bk][bjoff + 4] = b1;
        __syncthreads();

        #pragma unroll
        for (int kk = 0; kk < BK; kk++) {
            float4 bv = *(const float4*)&Bs[kk][tx * 4];
            float a_0 = As[ty * 4 + 0][kk];
            float a_1 = As[ty * 4 + 1][kk];
            float a_2 = As[ty * 4 + 2][kk];
            float a_3 = As[ty * 4 + 3][kk];
            acc[0][0] += a_0 * bv.x; acc[0][1] += a_0 * bv.y;
            acc[0][2] += a_0 * bv.z; acc[0][3] += a_0 * bv.w;
            acc[1][0] += a_1 * bv.x; acc[1][1] += a_1 * bv.y;
            acc[1][2] += a_1 * bv.z; acc[1][3] += a_1 * bv.w;
            acc[2][0] += a_2 * bv.x; acc[2][1] += a_2 * bv.y;
            acc[2][2] += a_2 * bv.z; acc[2][3] += a_2 * bv.w;
            acc[3][0] += a_3 * bv.x; acc[3][1] += a_3 * bv.y;
            acc[3][2] += a_3 * bv.z; acc[3][3] += a_3 * bv.w;
        }
        __syncthreads();
    }

    // Row-sum reduction: 4 threads (same arow) hold complementary k partials
    if (rowsum != nullptr && blockIdx.x == 0) {
        rsum += __shfl_down_sync(0xffffffffu, rsum, 2);
        rsum += __shfl_down_sync(0xffffffffu, rsum, 1);
        if ((t & 3) == 0) rowsum[rowBase + arow] = rsum;
    }

    #pragma unroll
    for (int i = 0; i < 4; i++) {
        float4 o;
        o.x = acc[i][0]; o.y = acc[i][1]; o.z = acc[i][2]; o.w = acc[i][3];
        *(float4*)&Y[(size_t)(rowBase + ty * 4 + i) * DD + colBase + tx * 4] = o;
    }
}

// out[i][:] = (X[i][:] + Yv[i][:]) / (rowsum[i] + 1)
__global__ void combine_kernel(const float* __restrict__ X,
                               const float* __restrict__ Yv,
                               const float* __restrict__ rs,
                               float* __restrict__ O)
{
    int i = blockIdx.x * blockDim.x + threadIdx.x;   // float4 index
    int row = i >> 6;                                 // 64 float4 per row
    float r = 1.0f / (rs[row] + 1.0f);
    float4 x = ((const float4*)X)[i];
    float4 y = ((const float4*)Yv)[i];
    float4 o;
    o.x = (x.x + y.x) * r; o.y = (x.y + y.y) * r;
    o.z = (x.z + y.z) * r; o.w = (x.w + y.w) * r;
    ((float4*)O)[i] = o;
}

__global__ void set_deg_kernel(float* __restrict__ deg)
{
    int i = blockIdx.x * blockDim.x + threadIdx.x;
    if (i < NN) deg[i] = 1.0f;
}

__global__ void deg_acc_kernel(const int* __restrict__ dst, float* __restrict__ deg)
{
    int e = blockIdx.x * blockDim.x + threadIdx.x;
    if (e < EE) atomicAdd(&deg[dst[e]], 1.0f);
}

__global__ void dinv_kernel(float* __restrict__ deg)
{
    int i = blockIdx.x * blockDim.x + threadIdx.x;
    if (i < NN) deg[i] = rsqrtf(deg[i]);
}

// out[i][d] = dinv[i]^2 * h[i][d] + b[d]   (self-loop term + bias)
__global__ void init_out_kernel(const float* __restrict__ h,
                                const float* __restrict__ dinv,
                                const float* __restrict__ b,
                                float* __restrict__ out)
{
    int i = blockIdx.x * blockDim.x + threadIdx.x;   // float4 index
    int row = i >> 6;
    float di = dinv[row];
    float c = di * di;
    float4 hv = ((const float4*)h)[i];
    float4 bv = *(const float4*)(b + ((i & 63) << 2));
    float4 o;
    o.x = c * hv.x + bv.x; o.y = c * hv.y + bv.y;
    o.z = c * hv.z + bv.z; o.w = c * hv.w + bv.w;
    ((float4*)out)[i] = o;
}

// One warp per edge: out[dst] += dinv[src]*dinv[dst] * h[src]
__global__ __launch_bounds__(256) void scatter_kernel(
    const int* __restrict__ src, const int* __restrict__ dst,
    const float* __restrict__ dinv,
    const float* __restrict__ h, float* __restrict__ out)
{
    int warp = blockIdx.x * (blockDim.x >> 5) + (threadIdx.x >> 5);
    if (warp >= EE) return;
    int lane = threadIdx.x & 31;
    int s = src[warp];
    int d = dst[warp];
    float c = dinv[s] * dinv[d];
    const float4* hs = (const float4*)(h + (size_t)s * DD);
    float* od = out + (size_t)d * DD;
    float4 v0 = hs[lane];
    float4 v1 = hs[lane + 32];
    int j0 = lane * 4;
    atomicAdd(&od[j0 + 0], c * v0.x);
    atomicAdd(&od[j0 + 1], c * v0.y);
    atomicAdd(&od[j0 + 2], c * v0.z);
    atomicAdd(&od[j0 + 3], c * v0.w);
    int j1 = (lane + 32) * 4;
    atomicAdd(&od[j1 + 0], c * v1.x);
    atomicAdd(&od[j1 + 1], c * v1.y);
    atomicAdd(&od[j1 + 2], c * v1.z);
    atomicAdd(&od[j1 + 3], c * v1.w);
}

extern "C" void kernel_launch(void* const* d_in, const int* in_sizes, int n_in,
                              void* d_out, int out_size)
{
    const float* emb    = (const float*)d_in[0];                // [N, 256]
    const float* Apath  = (const float*)d_in[1];                // [2, N, N]
    const int*   same   = (const int*)d_in[2];                  // [2, E]
    const int*   up     = (const int*)d_in[3];                  // [2, E]
    const float* Wsame  = (const float*)d_in[4];                // [256, 256]
    const float* bsame  = (const float*)d_in[5];                // [256]
    const float* Wtop   = (const float*)d_in[6];                // [256, 256]
    const float* btop   = (const float*)d_in[7];                // [256]
    float* out = (float*)d_out;

    float *gY, *gE, *gRS, *gDeg;
    cudaGetSymbolAddress((void**)&gY,   g_bufY);
    cudaGetSymbolAddress((void**)&gE,   g_bufE);
    cudaGetSymbolAddress((void**)&gRS,  g_rowsum);
    cudaGetSymbolAddress((void**)&gDeg, g_deg);

    dim3 mmGrid(DD / BN, NN / BM);       // (4, 128)
    int ew = (NN * DD / 4) / 256;        // elementwise grid (float4), 2048 blocks

    // ---- bottom_to_up level 0
    mm_kernel<<<mmGrid, 256>>>(Apath, NN, emb, gY, NN, gRS);
    combine_kernel<<<ew, 256>>>(emb, gY, gRS, gE);
    // ---- bottom_to_up level 1
    mm_kernel<<<mmGrid, 256>>>(Apath + (size_t)NN * NN, NN, gE, gY, NN, gRS);
    combine_kernel<<<ew, 256>>>(gE, gY, gRS, gE);

    // ---- GCNConv 1 (same-level)
    mm_kernel<<<mmGrid, 256>>>(gE, DD, Wsame, gY, DD, nullptr);   // h = emb @ W
    set_deg_kernel<<<NN / 256, 256>>>(gDeg);
    deg_acc_kernel<<<EE / 256, 256>>>(same + EE, gDeg);           // dst row
    dinv_kernel<<<NN / 256, 256>>>(gDeg);
    init_out_kernel<<<ew, 256>>>(gY, gDeg, bsame, gE);            // overwrite emb buf
    scatter_kernel<<<EE / 8, 256>>>(same, same + EE, gDeg, gY, gE);

    // ---- GCNConv 2 (top-to-bottom) -> d_out
    mm_kernel<<<mmGrid, 256>>>(gE, DD, Wtop, gY, DD, nullptr);    // h = emb @ W_top
    set_deg_kernel<<<NN / 256, 256>>>(gDeg);
    deg_acc_kernel<<<EE / 256, 256>>>(up + EE, gDeg);
    dinv_kernel<<<NN / 256, 256>>>(gDeg);
    init_out_kernel<<<ew, 256>>>(gY, gDeg, btop, out);
    scatter_kernel<<<EE / 8, 256>>>(up, up + EE, gDeg, gY, out);
}

// round 3
// speedup vs baseline: 2.4076x; 2.4076x over previous
#include <cuda_runtime.h>
#include <cuda_bf16.h>
#include <cstdint>

#define NN 8192
#define DD 256
#define EE 131072

#define SMEM_SWIZZLE_128B(o) ((o) ^ (((o) >> 3) & 0x70))

// ---------------------------------------------------------------------------
// Scratch (static device allocations — allowed)
// ---------------------------------------------------------------------------
__device__ float g_E1[NN * DD];
__device__ float g_H[NN * DD];
__device__ __nv_bfloat16 g_Bth[DD * NN];
__device__ __nv_bfloat16 g_Btl[DD * NN];
__device__ float g_deg[NN];

// ---------------------------------------------------------------------------
// PTX wrappers (sm_80-era instructions only: mma.sync / ldmatrix / cp.async)
// ---------------------------------------------------------------------------
__device__ __forceinline__ uint32_t smem_to_u32(const void* p) {
    uint32_t a;
    asm("{ .reg .u64 t; cvta.to.shared.u64 t, %1; cvt.u32.u64 %0, t; }" : "=r"(a) : "l"(p));
    return a;
}
__device__ __forceinline__ void ldsm4(uint32_t& r0, uint32_t& r1, uint32_t& r2, uint32_t& r3,
                                      uint32_t addr) {
    asm volatile("ldmatrix.sync.aligned.m8n8.x4.shared.b16 {%0,%1,%2,%3}, [%4];"
                 : "=r"(r0), "=r"(r1), "=r"(r2), "=r"(r3) : "r"(addr));
}
__device__ __forceinline__ void mma16816(float* c, const uint32_t* a, uint32_t b0, uint32_t b1) {
    asm volatile(
        "mma.sync.aligned.m16n8k16.row.col.f32.bf16.bf16.f32 "
        "{%0,%1,%2,%3}, {%4,%5,%6,%7}, {%8,%9}, {%0,%1,%2,%3};"
        : "+f"(c[0]), "+f"(c[1]), "+f"(c[2]), "+f"(c[3])
        : "r"(a[0]), "r"(a[1]), "r"(a[2]), "r"(a[3]), "r"(b0), "r"(b1));
}
#define CP_ASYNC16(dst, src) \
    asm volatile("cp.async.cg.shared.global [%0], [%1], 16;" :: "r"(dst), "l"(src))
#define CP_COMMIT() asm volatile("cp.async.commit_group;" ::: "memory")
#define CP_WAIT1() asm volatile("cp.async.wait_group 1;" ::: "memory")
#define CP_WAIT0() asm volatile("cp.async.wait_group 0;" ::: "memory")

// ---------------------------------------------------------------------------
// fp32 pair-of-float4 -> bf16 hi / lo packed uint4
// ---------------------------------------------------------------------------
__device__ __forceinline__ void cvt8(const float4 x, const float4 y, uint4& hi, uint4& lo) {
    __nv_bfloat162 h0 = __floats2bfloat162_rn(x.x, x.y);
    __nv_bfloat162 h1 = __floats2bfloat162_rn(x.z, x.w);
    __nv_bfloat162 h2 = __floats2bfloat162_rn(y.x, y.y);
    __nv_bfloat162 h3 = __floats2bfloat162_rn(y.z, y.w);
    hi.x = *(uint32_t*)&h0; hi.y = *(uint32_t*)&h1;
    hi.z = *(uint32_t*)&h2; hi.w = *(uint32_t*)&h3;
    float2 f0 = __bfloat1622float2(h0);
    float2 f1 = __bfloat1622float2(h1);
    float2 f2 = __bfloat1622float2(h2);
    float2 f3 = __bfloat1622float2(h3);
    __nv_bfloat162 l0 = __floats2bfloat162_rn(x.x - f0.x, x.y - f0.y);
    __nv_bfloat162 l1 = __floats2bfloat162_rn(x.z - f1.x, x.w - f1.y);
    __nv_bfloat162 l2 = __floats2bfloat162_rn(y.x - f2.x, y.y - f2.y);
    __nv_bfloat162 l3 = __floats2bfloat162_rn(y.z - f3.x, y.w - f3.y);
    lo.x = *(uint32_t*)&l0; lo.y = *(uint32_t*)&l1;
    lo.z = *(uint32_t*)&l2; lo.w = *(uint32_t*)&l3;
}

// ---------------------------------------------------------------------------
// Transpose-convert X[8192,256] fp32 -> T_hi/lo [256,8192] bf16
// ---------------------------------------------------------------------------
__global__ void tconv_kernel(const float* __restrict__ X,
                             __nv_bfloat16* __restrict__ Th,
                             __nv_bfloat16* __restrict__ Tl) {
    size_t i = (size_t)blockIdx.x * blockDim.x + threadIdx.x;  // i = n*8192 + k
    int n = (int)(i >> 13);
    int k = (int)(i & 8191);
    float v = X[(size_t)k * DD + n];
    __nv_bfloat16 h = __float2bfloat16(v);
    Th[i] = h;
    Tl[i] = __float2bfloat16(v - __bfloat162float(h));
}

// ---------------------------------------------------------------------------
// Big fused GEMM: Out = (Res + A @ X) / (rowsum(A)+1)
//   A [8192,8192] fp32 streamed, split bf16 hi/lo in-kernel
//   X as Bth/Btl [256,8192] bf16 (col-major k x n operand)
//   CTA tile M=128 N=128, BK=64, double-buffered, mma.sync 3-pass split.
// ---------------------------------------------------------------------------
#define KTOT 8192
#define CH 64
#define NCHUNK (KTOT / CH)
#define BUF_BYTES 65536
#define GEMM_SMEM (1024 + 2 * BUF_BYTES)

__global__ __launch_bounds__(256, 1) void gemm_big(
    const float* __restrict__ A,
    const __nv_bfloat16* __restrict__ Bth, const __nv_bfloat16* __restrict__ Btl,
    const float* __restrict__ Res,
    float* __restrict__ OutF)
{
    extern __shared__ char sm[];
    uint32_t smb = smem_to_u32(sm);
    const int t = threadIdx.x;
    const int lane = t & 31;
    const int w = t >> 5;
    const int m0 = blockIdx.y * 128;
    const int n0 = blockIdx.x * 128;
    const int wm = (w >> 2) * 64;      // warp M offset (0 / 64)
    const int wn = (w & 3) * 32;       // warp N offset (0/32/64/96)

    // --- A producer mapping: row = t>>1 (0..127), koff = (t&1)*32 elements
    const int arow = t >> 1;
    const int koff = (t & 1) * 32;
    const float* Ap = A + (size_t)(m0 + arow) * KTOT + koff;
    const uint32_t roff = arow * 128 + koff * 2;

    // --- B cp.async mapping: 1024 16B-chunks per 16KB tile, 4 per thread
    // chunk idx = t + i*256 -> row = idx>>3, seg = idx&7
    const __nv_bfloat16* BhG = Bth + (size_t)n0 * KTOT;
    const __nv_bfloat16* BlG = Btl + (size_t)n0 * KTOT;

    // --- fragment ldmatrix lane addressing (byte offsets inside tiles)
    const int a_r = lane & 15;
    const int a_c = (lane & 16) >> 1;            // 0 or 8 (elements)
    const int b_r = (lane & 7) + ((lane >> 4) << 3);
    const int b_c = lane & 8;                    // 0 or 8 (elements)

    float acc[4][4][4];
    #pragma unroll
    for (int i = 0; i < 4; i++)
        #pragma unroll
        for (int j = 0; j < 4; j++)
            #pragma unroll
            for (int q = 0; q < 4; q++) acc[i][j][q] = 0.0f;

    float4 aR[8];
    #pragma unroll
    for (int j = 0; j < 8; j++) aR[j] = *(const float4*)(Ap + j * 4);

    // prologue: B chunk 0 -> buf0
    {
        char* buf = sm + 1024;
        #pragma unroll
        for (int i = 0; i < 4; i++) {
            int idx = t + i * 256;
            int row = idx >> 3, seg = idx & 7;
            uint32_t so = SMEM_SWIZZLE_128B((uint32_t)(row * 128 + seg * 16));
            CP_ASYNC16(smb + 1024 + 32768 + so, BhG + (size_t)row * KTOT + seg * 8);
            CP_ASYNC16(smb + 1024 + 49152 + so, BlG + (size_t)row * KTOT + seg * 8);
        }
        (void)buf;
        CP_COMMIT();
    }

    float rsum = 0.0f;

    for (int c = 0; c < NCHUNK; c++) {
        const int b = c & 1;
        char* buf = sm + 1024 + b * BUF_BYTES;
        const uint32_t bufb = smb + 1024 + b * BUF_BYTES;

        // store A chunk c (convert + rowsum)
        #pragma unroll
        for (int j = 0; j < 4; j++) {
            float4 x = aR[2 * j], y = aR[2 * j + 1];
            rsum += x.x + x.y + x.z + x.w + y.x + y.y + y.z + y.w;
            uint4 hi, lo;
            cvt8(x, y, hi, lo);
            uint32_t o = SMEM_SWIZZLE_128B(roff + j * 16);
            *(uint4*)(buf + o)         = hi;
            *(uint4*)(buf + 16384 + o) = lo;
        }
        __syncthreads();   // S1: all mma reads of buf b^1 (iter c-1) complete

        if (c + 1 < NCHUNK) {
            // B chunk c+1 -> other buffer
            uint32_t obuf = smb + 1024 + (b ^ 1) * BUF_BYTES;
            const __nv_bfloat16* bh2 = BhG + (c + 1) * CH;
            const __nv_bfloat16* bl2 = BlG + (c + 1) * CH;
            #pragma unroll
            for (int i = 0; i < 4; i++) {
                int idx = t + i * 256;
                int row = idx >> 3, seg = idx & 7;
                uint32_t so = SMEM_SWIZZLE_128B((uint32_t)(row * 128 + seg * 16));
                CP_ASYNC16(obuf + 32768 + so, bh2 + (size_t)row * KTOT + seg * 8);
                CP_ASYNC16(obuf + 49152 + so, bl2 + (size_t)row * KTOT + seg * 8);
            }
            CP_COMMIT();
            // A chunk c+1 -> regs
            const float* Ap2 = Ap + (c + 1) * CH;
            #pragma unroll
            for (int j = 0; j < 8; j++) aR[j] = *(const float4*)(Ap2 + j * 4);
            CP_WAIT1();   // B chunk c arrived (this thread's part)
        } else {
            CP_WAIT0();
        }
        __syncthreads();   // S2: everyone's B chunk c visible; A stores visible

        // ---- compute 4 k16 steps x 3 passes
        const uint32_t Ah = bufb;
        const uint32_t Al = bufb + 16384;
        const uint32_t Bh = bufb + 32768;
        const uint32_t Bl = bufb + 49152;
        #pragma unroll
        for (int ks = 0; ks < 4; ks++) {
            const int kb = ks * 16;
            uint32_t ah[4][4], al[4][4], bh[2][4], bl[2][4];
            #pragma unroll
            for (int mt = 0; mt < 4; mt++) {
                uint32_t o = SMEM_SWIZZLE_128B((uint32_t)((wm + mt * 16 + a_r) * 128 + (kb + a_c) * 2));
                ldsm4(ah[mt][0], ah[mt][1], ah[mt][2], ah[mt][3], Ah + o);
                ldsm4(al[mt][0], al[mt][1], al[mt][2], al[mt][3], Al + o);
            }
            #pragma unroll
            for (int p = 0; p < 2; p++) {
                uint32_t o = SMEM_SWIZZLE_128B((uint32_t)((wn + p * 16 + b_r) * 128 + (kb + b_c) * 2));
                ldsm4(bh[p][0], bh[p][1], bh[p][2], bh[p][3], Bh + o);
                ldsm4(bl[p][0], bl[p][1], bl[p][2], bl[p][3], Bl + o);
            }
            #pragma unroll
            for (int mt = 0; mt < 4; mt++) {
                #pragma unroll
                for (int nt = 0; nt < 4; nt++) {
                    uint32_t bh0 = bh[nt >> 1][(nt & 1) * 2];
                    uint32_t bh1 = bh[nt >> 1][(nt & 1) * 2 + 1];
                    uint32_t bl0 = bl[nt >> 1][(nt & 1) * 2];
                    uint32_t bl1 = bl[nt >> 1][(nt & 1) * 2 + 1];
                    mma16816(acc[mt][nt], ah[mt], bh0, bh1);
                    mma16816(acc[mt][nt], ah[mt], bl0, bl1);
                    mma16816(acc[mt][nt], al[mt], bh0, bh1);
                }
            }
        }
    }

    // ---- rowsum -> smem (pair (2r,2r+1) covers full row r)
    float rs2 = rsum + __shfl_xor_sync(0xffffffffu, rsum, 1);
    float* rsm = (float*)(sm + 256);
    if (!(t & 1)) rsm[arow] = rs2;
    __syncthreads();

    // ---- epilogue: (Res + acc) * 1/(rs+1)
    const int lq = lane >> 2;      // 0..7
    const int lr = lane & 3;       // col pair idx
    #pragma unroll
    for (int mt = 0; mt < 4; mt++) {
        int rA = wm + mt * 16 + lq;
        int rB = rA + 8;
        float riA = 1.0f / (rsm[rA] + 1.0f);
        float riB = 1.0f / (rsm[rB] + 1.0f);
        #pragma unroll
        for (int nt = 0; nt < 4; nt++) {
            int col = n0 + wn + nt * 8 + lr * 2;
            float* a4 = acc[mt][nt];
            size_t gA = (size_t)(m0 + rA) * DD + col;
            size_t gB = (size_t)(m0 + rB) * DD + col;
            float2 resA = *(const float2*)(Res + gA);
            float2 resB = *(const float2*)(Res + gB);
            float2 oA, oB;
            oA.x = (resA.x + a4[0]) * riA;
            oA.y = (resA.y + a4[1]) * riA;
            oB.x = (resB.x + a4[2]) * riB;
            oB.y = (resB.y + a4[3]) * riB;
            *(float2*)(OutF + gA) = oA;
            *(float2*)(OutF + gB) = oB;
        }
    }
}

// ---------------------------------------------------------------------------
// fp32 SIMT matmul for the small GCN matmuls: Y[8192,256] = A[8192,K] @ B[K,256]
// ---------------------------------------------------------------------------
#define BM 64
#define BN 64
#define BK 32
__global__ __launch_bounds__(256) void mm_kernel(
    const float* __restrict__ A, int lda,
    const float* __restrict__ B,
    float* __restrict__ Y, int K)
{
    __shared__ float As[BM][BK + 4];
    __shared__ float Bs[BK][BN];
    const int t = threadIdx.x;
    const int rowBase = blockIdx.y * BM;
    const int colBase = blockIdx.x * BN;
    const int tx = t & 15;
    const int ty = t >> 4;
    const int arow  = t >> 2;
    const int akoff = (t & 3) * 8;
    const int bk    = t >> 3;
    const int bjoff = (t & 7) * 8;

    float acc[4][4] = {};
    const float* Aptr = A + (size_t)(rowBase + arow) * lda + akoff;
    const float* Bptr = B + (size_t)bk * DD + colBase + bjoff;

    for (int k0 = 0; k0 < K; k0 += BK) {
        float4 a0 = *(const float4*)(Aptr + k0);
        float4 a1 = *(const float4*)(Aptr + k0 + 4);
        *(float4*)&As[arow][akoff]     = a0;
        *(float4*)&As[arow][akoff + 4] = a1;
        float4 b0 = *(const float4*)(Bptr + (size_t)k0 * DD);
        float4 b1 = *(const float4*)(Bptr + (size_t)k0 * DD + 4);
        *(float4*)&Bs[bk][bjoff]     = b0;
        *(float4*)&Bs[bk][bjoff + 4] = b1;
        __syncthreads();
        #pragma unroll
        for (int kk = 0; kk < BK; kk++) {
            float4 bv = *(const float4*)&Bs[kk][tx * 4];
            float a_0 = As[ty * 4 + 0][kk];
            float a_1 = As[ty * 4 + 1][kk];
            float a_2 = As[ty * 4 + 2][kk];
            float a_3 = As[ty * 4 + 3][kk];
            acc[0][0] += a_0 * bv.x; acc[0][1] += a_0 * bv.y;
            acc[0][2] += a_0 * bv.z; acc[0][3] += a_0 * bv.w;
            acc[1][0] += a_1 * bv.x; acc[1][1] += a_1 * bv.y;
            acc[1][2] += a_1 * bv.z; acc[1][3] += a_1 * bv.w;
            acc[2][0] += a_2 * bv.x; acc[2][1] += a_2 * bv.y;
            acc[2][2] += a_2 * bv.z; acc[2][3] += a_2 * bv.w;
            acc[3][0] += a_3 * bv.x; acc[3][1] += a_3 * bv.y;
            acc[3][2] += a_3 * bv.z; acc[3][3] += a_3 * bv.w;
        }
        __syncthreads();
    }
    #pragma unroll
    for (int i = 0; i < 4; i++) {
        float4 o;
        o.x = acc[i][0]; o.y = acc[i][1]; o.z = acc[i][2]; o.w = acc[i][3];
        *(float4*)&Y[(size_t)(rowBase + ty * 4 + i) * DD + colBase + tx * 4] = o;
    }
}

// ---------------------------------------------------------------------------
// GCN degree / epilogue / scatter kernels
// ---------------------------------------------------------------------------
__global__ void set_deg_kernel(float* __restrict__ deg) {
    int i = blockIdx.x * blockDim.x + threadIdx.x;
    if (i < NN) deg[i] = 1.0f;
}
__global__ void deg_acc_kernel(const int* __restrict__ dst, float* __restrict__ deg) {
    int e = blockIdx.x * blockDim.x + threadIdx.x;
    if (e < EE) atomicAdd(&deg[dst[e]], 1.0f);
}
__global__ void dinv_kernel(float* __restrict__ deg) {
    int i = blockIdx.x * blockDim.x + threadIdx.x;
    if (i < NN) deg[i] = rsqrtf(deg[i]);
}
__global__ void init_out_kernel(const float* __restrict__ h,
                                const float* __restrict__ dinv,
                                const float* __restrict__ b,
                                float* __restrict__ out) {
    int i = blockIdx.x * blockDim.x + threadIdx.x;
    int row = i >> 6;
    float di = dinv[row];
    float c = di * di;
    float4 hv = ((const float4*)h)[i];
    float4 bv = *(const float4*)(b + ((i & 63) << 2));
    float4 o;
    o.x = c * hv.x + bv.x; o.y = c * hv.y + bv.y;
    o.z = c * hv.z + bv.z; o.w = c * hv.w + bv.w;
    ((float4*)out)[i] = o;
}
__global__ __launch_bounds__(256) void scatter_kernel(
    const int* __restrict__ src, const int* __restrict__ dst,
    const float* __restrict__ dinv,
    const float* __restrict__ h, float* __restrict__ out) {
    int warp = blockIdx.x * (blockDim.x >> 5) + (threadIdx.x >> 5);
    if (warp >= EE) return;
    int lane = threadIdx.x & 31;
    int s = src[warp];
    int d = dst[warp];
    float c = dinv[s] * dinv[d];
    const float4* hs = (const float4*)(h + (size_t)s * DD);
    float* od = out + (size_t)d * DD;
    float4 v0 = hs[lane];
    float4 v1 = hs[lane + 32];
    int j0 = lane * 4;
    atomicAdd(&od[j0 + 0], c * v0.x);
    atomicAdd(&od[j0 + 1], c * v0.y);
    atomicAdd(&od[j0 + 2], c * v0.z);
    atomicAdd(&od[j0 + 3], c * v0.w);
    int j1 = (lane + 32) * 4;
    atomicAdd(&od[j1 + 0], c * v1.x);
    atomicAdd(&od[j1 + 1], c * v1.y);
    atomicAdd(&od[j1 + 2], c * v1.z);
    atomicAdd(&od[j1 + 3], c * v1.w);
}

// ---------------------------------------------------------------------------
extern "C" void kernel_launch(void* const* d_in, const int* in_sizes, int n_in,
                              void* d_out, int out_size)
{
    const float* emb   = (const float*)d_in[0];
    const float* Apath = (const float*)d_in[1];
    const int*   same  = (const int*)d_in[2];
    const int*   up    = (const int*)d_in[3];
    const float* Wsame = (const float*)d_in[4];
    const float* bsame = (const float*)d_in[5];
    const float* Wtop  = (const float*)d_in[6];
    const float* btop  = (const float*)d_in[7];
    float* out = (float*)d_out;

    float *gE1, *gH, *gDeg;
    __nv_bfloat16 *gBh, *gBl;
    cudaGetSymbolAddress((void**)&gE1,  g_E1);
    cudaGetSymbolAddress((void**)&gH,   g_H);
    cudaGetSymbolAddress((void**)&gDeg, g_deg);
    cudaGetSymbolAddress((void**)&gBh,  g_Bth);
    cudaGetSymbolAddress((void**)&gBl,  g_Btl);

    cudaFuncSetAttribute(gemm_big, cudaFuncAttributeMaxDynamicSharedMemorySize, GEMM_SMEM);

    dim3 gGrid(2, 64);
    dim3 mmGrid(DD / BN, NN / BM);
    int ew = (NN * DD / 4) / 256;

    // Level 0
    tconv_kernel<<<(NN * DD) / 256, 256>>>(emb, gBh, gBl);
    gemm_big<<<gGrid, 256, GEMM_SMEM>>>(Apath, gBh, gBl, emb, gE1);
    // Level 1 (in-place on E1)
    tconv_kernel<<<(NN * DD) / 256, 256>>>(gE1, gBh, gBl);
    gemm_big<<<gGrid, 256, GEMM_SMEM>>>(Apath + (size_t)NN * NN, gBh, gBl, gE1, gE1);

    // GCNConv 1 (same-level)
    mm_kernel<<<mmGrid, 256>>>(gE1, DD, Wsame, gH, DD);
    set_deg_kernel<<<NN / 256, 256>>>(gDeg);
    deg_acc_kernel<<<EE / 256, 256>>>(same + EE, gDeg);
    dinv_kernel<<<NN / 256, 256>>>(gDeg);
    init_out_kernel<<<ew, 256>>>(gH, gDeg, bsame, gE1);
    scatter_kernel<<<EE / 8, 256>>>(same, same + EE, gDeg, gH, gE1);

    // GCNConv 2 (top-to-bottom) -> d_out
    mm_kernel<<<mmGrid, 256>>>(gE1, DD, Wtop, gH, DD);
    set_deg_kernel<<<NN / 256, 256>>>(gDeg);
    deg_acc_kernel<<<EE / 256, 256>>>(up + EE, gDeg);
    dinv_kernel<<<NN / 256, 256>>>(gDeg);
    init_out_kernel<<<ew, 256>>>(gH, gDeg, btop, out);
    scatter_kernel<<<EE / 8, 256>>>(up, up + EE, gDeg, gH, out);
}